// round 5
// baseline (speedup 1.0000x reference)
#include <cuda_runtime.h>
#include <cuda_bf16.h>
#include <cstdint>

// Problem constants
#define B_  16
#define C_  512
#define N_  1024
#define D_  64

// Scratch (device globals per allocation rules): 4 + 4 + 32 + 64 = 104 MB
__device__ float g_q[(size_t)B_ * N_ * D_];              // [b][n][d]
__device__ float g_k[(size_t)B_ * N_ * D_];              // [b][n][d]
__device__ float g_v[(size_t)B_ * N_ * C_];              // vT: [b][m][c]
__device__ float g_attn[(size_t)B_ * N_ * N_];           // [b][n][m]

typedef unsigned long long ull;

__device__ __forceinline__ ull pk2(float lo, float hi) {
    ull r; asm("mov.b64 %0, {%1, %2};" : "=l"(r) : "f"(lo), "f"(hi)); return r;
}
__device__ __forceinline__ float2 up2(ull v) {
    float2 r; asm("mov.b64 {%0, %1}, %2;" : "=f"(r.x), "=f"(r.y) : "l"(v)); return r;
}
__device__ __forceinline__ void fma2(ull& d, ull a, ull b) {
    asm("fma.rn.f32x2 %0, %1, %2, %0;" : "+l"(d) : "l"(a), "l"(b));
}

// ---------------------------------------------------------------------------
// Kernel 1: fused QKV projection.  Y[oc, n] = sum_c W[oc,c] * x[b,c,n] + bias
// Tile: 64 oc x 64 n, block 256 threads, 4x4 micro-tile, k-chunks of 16.
// oc0 = 0   -> Wq -> g_q   [b][n][0..64)
// oc0 = 64  -> Wk -> g_k   [b][n][0..64)
// oc0 >=128 -> Wv -> g_v   [b][n][oc0-128 ..)
// ---------------------------------------------------------------------------
__global__ __launch_bounds__(256) void k_proj(
    const float* __restrict__ x,
    const float* __restrict__ Wq, const float* __restrict__ bq,
    const float* __restrict__ Wk, const float* __restrict__ bk,
    const float* __restrict__ Wv, const float* __restrict__ bv)
{
    __shared__ float sA[16][132];  // W tile, value-duplicated: [kk][2*ocl {lo,hi}]
    __shared__ float sB[16][68];   // x tile: [kk][nl]
    __shared__ float sO[64][65];   // output restage [nl][ocl]

    const int b   = blockIdx.z;
    const int oc0 = blockIdx.y * 64;
    const int n0  = blockIdx.x * 64;

    const float* Wsrc; const float* bias; float* dst; int dstride;
    if (oc0 == 0)       { Wsrc = Wq; bias = bq; dst = g_q + (size_t)b * N_ * D_; dstride = D_; }
    else if (oc0 == 64) { Wsrc = Wk; bias = bk; dst = g_k + (size_t)b * N_ * D_; dstride = D_; }
    else                { Wsrc = Wv + (size_t)(oc0 - 128) * C_; bias = bv + (oc0 - 128);
                          dst = g_v + (size_t)b * N_ * C_ + (oc0 - 128); dstride = C_; }

    const int t  = threadIdx.x;
    const int tx = t & 15, ty = t >> 4;

    // load mappings
    const int la_r = t >> 2;          // 0..63  W row within tile
    const int la_c = (t & 3) * 4;     // kk base
    const int lb_k = t >> 4;          // 0..15
    const int lb_n = (t & 15) * 4;    // 0,4,..,60

    const float* xb = x + (size_t)b * C_ * N_ + n0;

    ull acc[4][2];
#pragma unroll
    for (int i = 0; i < 4; ++i) { acc[i][0] = 0ULL; acc[i][1] = 0ULL; }

    for (int k0 = 0; k0 < C_; k0 += 16) {
        float4 w4 = *(const float4*)(Wsrc + (size_t)la_r * C_ + k0 + la_c);
        *(ull*)&sA[la_c + 0][2 * la_r] = pk2(w4.x, w4.x);
        *(ull*)&sA[la_c + 1][2 * la_r] = pk2(w4.y, w4.y);
        *(ull*)&sA[la_c + 2][2 * la_r] = pk2(w4.z, w4.z);
        *(ull*)&sA[la_c + 3][2 * la_r] = pk2(w4.w, w4.w);
        float4 x4 = *(const float4*)(xb + (size_t)(k0 + lb_k) * N_ + lb_n);
        *(float4*)&sB[lb_k][lb_n] = x4;
        __syncthreads();
#pragma unroll
        for (int kk = 0; kk < 16; ++kk) {
            const ull* ap = (const ull*)&sA[kk][ty * 8];
            const ull* bp = (const ull*)&sB[kk][tx * 4];
            ull b0 = bp[0], b1 = bp[1];
#pragma unroll
            for (int i = 0; i < 4; ++i) {
                ull a = ap[i];
                fma2(acc[i][0], a, b0);
                fma2(acc[i][1], a, b1);
            }
        }
        __syncthreads();
    }

    // bias + restage to smem for coalesced transposed write
    float4 bi4 = *(const float4*)(bias + ty * 4);
    float bia[4] = {bi4.x, bi4.y, bi4.z, bi4.w};
#pragma unroll
    for (int i = 0; i < 4; ++i) {
        float2 a0 = up2(acc[i][0]);
        float2 a1 = up2(acc[i][1]);
        sO[tx * 4 + 0][ty * 4 + i] = a0.x + bia[i];
        sO[tx * 4 + 1][ty * 4 + i] = a0.y + bia[i];
        sO[tx * 4 + 2][ty * 4 + i] = a1.x + bia[i];
        sO[tx * 4 + 3][ty * 4 + i] = a1.y + bia[i];
    }
    __syncthreads();
#pragma unroll
    for (int s = 0; s < 16; ++s) {
        int idx = s * 256 + t;
        int nl  = idx >> 6;
        int ocl = idx & 63;
        dst[(size_t)(n0 + nl) * dstride + ocl] = sO[nl][ocl];
    }
}

// ---------------------------------------------------------------------------
// Kernel 2: scores S[b,n,m] = sum_d q[b,n,d] * k[b,m,d]   (NT GEMM, K=64)
// ---------------------------------------------------------------------------
__global__ __launch_bounds__(256) void k_scores()
{
    __shared__ float sA[16][132];  // q tile duplicated: [kk][2*nl]
    __shared__ float sB[16][68];   // k tile transposed: [kk][ml]

    const int b  = blockIdx.z;
    const int n0 = blockIdx.y * 64;
    const int m0 = blockIdx.x * 64;

    const int t  = threadIdx.x;
    const int tx = t & 15, ty = t >> 4;
    const int lr = t >> 2;          // 0..63 row within tile
    const int lc = (t & 3) * 4;     // kk base

    const float* qb = g_q + (size_t)b * N_ * D_;
    const float* kb = g_k + (size_t)b * N_ * D_;

    ull acc[4][2];
#pragma unroll
    for (int i = 0; i < 4; ++i) { acc[i][0] = 0ULL; acc[i][1] = 0ULL; }

    for (int k0 = 0; k0 < D_; k0 += 16) {
        float4 q4 = *(const float4*)(qb + (size_t)(n0 + lr) * D_ + k0 + lc);
        *(ull*)&sA[lc + 0][2 * lr] = pk2(q4.x, q4.x);
        *(ull*)&sA[lc + 1][2 * lr] = pk2(q4.y, q4.y);
        *(ull*)&sA[lc + 2][2 * lr] = pk2(q4.z, q4.z);
        *(ull*)&sA[lc + 3][2 * lr] = pk2(q4.w, q4.w);
        float4 k4 = *(const float4*)(kb + (size_t)(m0 + lr) * D_ + k0 + lc);
        sB[lc + 0][lr] = k4.x;
        sB[lc + 1][lr] = k4.y;
        sB[lc + 2][lr] = k4.z;
        sB[lc + 3][lr] = k4.w;
        __syncthreads();
#pragma unroll
        for (int kk = 0; kk < 16; ++kk) {
            const ull* ap = (const ull*)&sA[kk][ty * 8];
            const ull* bp = (const ull*)&sB[kk][tx * 4];
            ull b0 = bp[0], b1 = bp[1];
#pragma unroll
            for (int i = 0; i < 4; ++i) {
                ull a = ap[i];
                fma2(acc[i][0], a, b0);
                fma2(acc[i][1], a, b1);
            }
        }
        __syncthreads();
    }

    float* Sb = g_attn + (size_t)b * N_ * N_;
#pragma unroll
    for (int i = 0; i < 4; ++i) {
        float2 a0 = up2(acc[i][0]);
        float2 a1 = up2(acc[i][1]);
        *(float4*)(Sb + (size_t)(n0 + ty * 4 + i) * N_ + m0 + tx * 4) =
            make_float4(a0.x, a0.y, a1.x, a1.y);
    }
}

// ---------------------------------------------------------------------------
// Kernel 3: row softmax over g_attn, in place. One block per (b, n) row.
// ---------------------------------------------------------------------------
__global__ __launch_bounds__(256) void k_softmax()
{
    float* p = g_attn + (size_t)blockIdx.x * N_;
    const int t = threadIdx.x;
    const int w = t >> 5, l = t & 31;
    __shared__ float red[8];

    float4 v = *(float4*)(p + t * 4);
    float m = fmaxf(fmaxf(v.x, v.y), fmaxf(v.z, v.w));
#pragma unroll
    for (int o = 16; o; o >>= 1) m = fmaxf(m, __shfl_xor_sync(0xffffffffu, m, o));
    if (l == 0) red[w] = m;
    __syncthreads();
    if (t == 0) {
        float mm = red[0];
#pragma unroll
        for (int i = 1; i < 8; ++i) mm = fmaxf(mm, red[i]);
        red[0] = mm;
    }
    __syncthreads();
    const float M = red[0];
    __syncthreads();

    v.x = __expf(v.x - M);
    v.y = __expf(v.y - M);
    v.z = __expf(v.z - M);
    v.w = __expf(v.w - M);
    float s = v.x + v.y + v.z + v.w;
#pragma unroll
    for (int o = 16; o; o >>= 1) s += __shfl_xor_sync(0xffffffffu, s, o);
    if (l == 0) red[w] = s;
    __syncthreads();
    if (t == 0) {
        float ss = red[0];
#pragma unroll
        for (int i = 1; i < 8; ++i) ss += red[i];
        red[0] = ss;
    }
    __syncthreads();
    const float inv = 1.0f / red[0];

    v.x *= inv; v.y *= inv; v.z *= inv; v.w *= inv;
    *(float4*)(p + t * 4) = v;
}

// ---------------------------------------------------------------------------
// Kernel 4: out[b,c,n] = gamma * sum_m attn[b,n,m] * vT[b,m,c] + x[b,c,n]
// Computed as O_T[c][n]: rows = c (from vT, contiguous dup load),
// cols = n (from attn, transposed load). Direct coalesced float4 epilogue.
// ---------------------------------------------------------------------------
__global__ __launch_bounds__(256) void k_out(
    const float* __restrict__ x, const float* __restrict__ gamma,
    float* __restrict__ out)
{
    __shared__ float sA[16][132];  // vT tile duplicated: [kk][2*cl]
    __shared__ float sB[16][68];   // attn tile transposed: [kk][nl]

    const int b  = blockIdx.z;
    const int c0 = blockIdx.y * 64;
    const int n0 = blockIdx.x * 64;

    const int t  = threadIdx.x;
    const int tx = t & 15, ty = t >> 4;

    // vT load mapping (contiguous in c)
    const int va_k = t >> 4;          // 0..15
    const int va_c = (t & 15) * 4;    // 0,4,..,60
    // attn load mapping (transposed)
    const int ab_n = t >> 2;          // 0..63
    const int ab_k = (t & 3) * 4;     // kk base

    const float* vb = g_v    + (size_t)b * N_ * C_ + c0;
    const float* Ab = g_attn + (size_t)b * N_ * N_;

    ull acc[4][2];
#pragma unroll
    for (int i = 0; i < 4; ++i) { acc[i][0] = 0ULL; acc[i][1] = 0ULL; }

    for (int k0 = 0; k0 < N_; k0 += 16) {
        float4 v4 = *(const float4*)(vb + (size_t)(k0 + va_k) * C_ + va_c);
        *(float4*)&sA[va_k][2 * va_c]     = make_float4(v4.x, v4.x, v4.y, v4.y);
        *(float4*)&sA[va_k][2 * va_c + 4] = make_float4(v4.z, v4.z, v4.w, v4.w);
        float4 a4 = *(const float4*)(Ab + (size_t)(n0 + ab_n) * N_ + k0 + ab_k);
        sB[ab_k + 0][ab_n] = a4.x;
        sB[ab_k + 1][ab_n] = a4.y;
        sB[ab_k + 2][ab_n] = a4.z;
        sB[ab_k + 3][ab_n] = a4.w;
        __syncthreads();
#pragma unroll
        for (int kk = 0; kk < 16; ++kk) {
            const ull* ap = (const ull*)&sA[kk][ty * 8];
            const ull* bp = (const ull*)&sB[kk][tx * 4];
            ull b0 = bp[0], b1 = bp[1];
#pragma unroll
            for (int i = 0; i < 4; ++i) {
                ull a = ap[i];
                fma2(acc[i][0], a, b0);
                fma2(acc[i][1], a, b1);
            }
        }
        __syncthreads();
    }

    const float gm = gamma[0];
#pragma unroll
    for (int i = 0; i < 4; ++i) {
        int c = c0 + ty * 4 + i;
        size_t off = ((size_t)b * C_ + c) * N_ + n0 + tx * 4;
        float4 xv = *(const float4*)(x + off);
        float2 a0 = up2(acc[i][0]);
        float2 a1 = up2(acc[i][1]);
        float4 o;
        o.x = fmaf(gm, a0.x, xv.x);
        o.y = fmaf(gm, a0.y, xv.y);
        o.z = fmaf(gm, a1.x, xv.z);
        o.w = fmaf(gm, a1.y, xv.w);
        *(float4*)(out + off) = o;
    }
}

// ---------------------------------------------------------------------------
extern "C" void kernel_launch(void* const* d_in, const int* in_sizes, int n_in,
                              void* d_out, int out_size)
{
    (void)in_sizes; (void)n_in; (void)out_size;
    const float* x     = (const float*)d_in[0];
    const float* Wq    = (const float*)d_in[1];
    const float* bq    = (const float*)d_in[2];
    const float* Wk    = (const float*)d_in[3];
    const float* bk    = (const float*)d_in[4];
    const float* Wv    = (const float*)d_in[5];
    const float* bv    = (const float*)d_in[6];
    const float* gamma = (const float*)d_in[7];
    float* out = (float*)d_out;

    k_proj<<<dim3(N_ / 64, 10, B_), 256>>>(x, Wq, bq, Wk, bk, Wv, bv);
    k_scores<<<dim3(N_ / 64, N_ / 64, B_), 256>>>();
    k_softmax<<<B_ * N_, 256>>>();
    k_out<<<dim3(N_ / 64, C_ / 64, B_), 256>>>(x, gamma, out);
}

// round 9
// speedup vs baseline: 1.0018x; 1.0018x over previous
#include <cuda_runtime.h>
#include <cuda_bf16.h>
#include <cstdint>

// Problem constants
#define B_  16
#define C_  512
#define N_  1024
#define D_  64

// Scratch (device globals per allocation rules): 4 + 4 + 32 + 64 = 104 MB
__device__ float g_q[(size_t)B_ * N_ * D_];              // [b][n][d]
__device__ float g_k[(size_t)B_ * N_ * D_];              // [b][n][d]
__device__ float g_v[(size_t)B_ * N_ * C_];              // vT: [b][m][c]
__device__ float g_attn[(size_t)B_ * N_ * N_];           // [b][n][m]

typedef unsigned long long ull;

__device__ __forceinline__ ull pk2(float lo, float hi) {
    ull r; asm("mov.b64 %0, {%1, %2};" : "=l"(r) : "f"(lo), "f"(hi)); return r;
}
__device__ __forceinline__ float2 up2(ull v) {
    float2 r; asm("mov.b64 {%0, %1}, %2;" : "=f"(r.x), "=f"(r.y) : "l"(v)); return r;
}
__device__ __forceinline__ void fma2(ull& d, ull a, ull b) {
    asm("fma.rn.f32x2 %0, %1, %2, %0;" : "+l"(d) : "l"(a), "l"(b));
}

// ---------------------------------------------------------------------------
// Kernel 1: fused QKV projection.  Y[oc, n] = sum_c W[oc,c] * x[b,c,n] + bias
// Tile: 64 oc x 64 n, block 256 threads, 4x4 micro-tile, k-chunks of 16.
// oc0 = 0   -> Wq -> g_q   [b][n][0..64)
// oc0 = 64  -> Wk -> g_k   [b][n][0..64)
// oc0 >=128 -> Wv -> g_v   [b][n][oc0-128 ..)
// ---------------------------------------------------------------------------
__global__ __launch_bounds__(256) void k_proj(
    const float* __restrict__ x,
    const float* __restrict__ Wq, const float* __restrict__ bq,
    const float* __restrict__ Wk, const float* __restrict__ bk,
    const float* __restrict__ Wv, const float* __restrict__ bv)
{
    __shared__ float sA[16][132];  // W tile, value-duplicated: [kk][2*ocl {lo,hi}]
    __shared__ float sB[16][68];   // x tile: [kk][nl]
    __shared__ float sO[64][65];   // output restage [nl][ocl]

    const int b   = blockIdx.z;
    const int oc0 = blockIdx.y * 64;
    const int n0  = blockIdx.x * 64;

    const float* Wsrc; const float* bias; float* dst; int dstride;
    if (oc0 == 0)       { Wsrc = Wq; bias = bq; dst = g_q + (size_t)b * N_ * D_; dstride = D_; }
    else if (oc0 == 64) { Wsrc = Wk; bias = bk; dst = g_k + (size_t)b * N_ * D_; dstride = D_; }
    else                { Wsrc = Wv + (size_t)(oc0 - 128) * C_; bias = bv + (oc0 - 128);
                          dst = g_v + (size_t)b * N_ * C_ + (oc0 - 128); dstride = C_; }

    const int t  = threadIdx.x;
    const int tx = t & 15, ty = t >> 4;

    // load mappings
    const int la_r = t >> 2;          // 0..63  W row within tile
    const int la_c = (t & 3) * 4;     // kk base
    const int lb_k = t >> 4;          // 0..15
    const int lb_n = (t & 15) * 4;    // 0,4,..,60

    const float* xb = x + (size_t)b * C_ * N_ + n0;

    ull acc[4][2];
#pragma unroll
    for (int i = 0; i < 4; ++i) { acc[i][0] = 0ULL; acc[i][1] = 0ULL; }

    for (int k0 = 0; k0 < C_; k0 += 16) {
        float4 w4 = *(const float4*)(Wsrc + (size_t)la_r * C_ + k0 + la_c);
        *(ull*)&sA[la_c + 0][2 * la_r] = pk2(w4.x, w4.x);
        *(ull*)&sA[la_c + 1][2 * la_r] = pk2(w4.y, w4.y);
        *(ull*)&sA[la_c + 2][2 * la_r] = pk2(w4.z, w4.z);
        *(ull*)&sA[la_c + 3][2 * la_r] = pk2(w4.w, w4.w);
        float4 x4 = *(const float4*)(xb + (size_t)(k0 + lb_k) * N_ + lb_n);
        *(float4*)&sB[lb_k][lb_n] = x4;
        __syncthreads();
#pragma unroll
        for (int kk = 0; kk < 16; ++kk) {
            const ull* ap = (const ull*)&sA[kk][ty * 8];
            const ull* bp = (const ull*)&sB[kk][tx * 4];
            ull b0 = bp[0], b1 = bp[1];
#pragma unroll
            for (int i = 0; i < 4; ++i) {
                ull a = ap[i];
                fma2(acc[i][0], a, b0);
                fma2(acc[i][1], a, b1);
            }
        }
        __syncthreads();
    }

    // bias + restage to smem for coalesced transposed write
    float4 bi4 = *(const float4*)(bias + ty * 4);
    float bia[4] = {bi4.x, bi4.y, bi4.z, bi4.w};
#pragma unroll
    for (int i = 0; i < 4; ++i) {
        float2 a0 = up2(acc[i][0]);
        float2 a1 = up2(acc[i][1]);
        sO[tx * 4 + 0][ty * 4 + i] = a0.x + bia[i];
        sO[tx * 4 + 1][ty * 4 + i] = a0.y + bia[i];
        sO[tx * 4 + 2][ty * 4 + i] = a1.x + bia[i];
        sO[tx * 4 + 3][ty * 4 + i] = a1.y + bia[i];
    }
    __syncthreads();
#pragma unroll
    for (int s = 0; s < 16; ++s) {
        int idx = s * 256 + t;
        int nl  = idx >> 6;
        int ocl = idx & 63;
        dst[(size_t)(n0 + nl) * dstride + ocl] = sO[nl][ocl];
    }
}

// ---------------------------------------------------------------------------
// Kernel 2: scores S[b,n,m] = sum_d q[b,n,d] * k[b,m,d]   (NT GEMM, K=64)
// ---------------------------------------------------------------------------
__global__ __launch_bounds__(256) void k_scores()
{
    __shared__ float sA[16][132];  // q tile duplicated: [kk][2*nl]
    __shared__ float sB[16][68];   // k tile transposed: [kk][ml]

    const int b  = blockIdx.z;
    const int n0 = blockIdx.y * 64;
    const int m0 = blockIdx.x * 64;

    const int t  = threadIdx.x;
    const int tx = t & 15, ty = t >> 4;
    const int lr = t >> 2;          // 0..63 row within tile
    const int lc = (t & 3) * 4;     // kk base

    const float* qb = g_q + (size_t)b * N_ * D_;
    const float* kb = g_k + (size_t)b * N_ * D_;

    ull acc[4][2];
#pragma unroll
    for (int i = 0; i < 4; ++i) { acc[i][0] = 0ULL; acc[i][1] = 0ULL; }

    for (int k0 = 0; k0 < D_; k0 += 16) {
        float4 q4 = *(const float4*)(qb + (size_t)(n0 + lr) * D_ + k0 + lc);
        *(ull*)&sA[lc + 0][2 * lr] = pk2(q4.x, q4.x);
        *(ull*)&sA[lc + 1][2 * lr] = pk2(q4.y, q4.y);
        *(ull*)&sA[lc + 2][2 * lr] = pk2(q4.z, q4.z);
        *(ull*)&sA[lc + 3][2 * lr] = pk2(q4.w, q4.w);
        float4 k4 = *(const float4*)(kb + (size_t)(m0 + lr) * D_ + k0 + lc);
        sB[lc + 0][lr] = k4.x;
        sB[lc + 1][lr] = k4.y;
        sB[lc + 2][lr] = k4.z;
        sB[lc + 3][lr] = k4.w;
        __syncthreads();
#pragma unroll
        for (int kk = 0; kk < 16; ++kk) {
            const ull* ap = (const ull*)&sA[kk][ty * 8];
            const ull* bp = (const ull*)&sB[kk][tx * 4];
            ull b0 = bp[0], b1 = bp[1];
#pragma unroll
            for (int i = 0; i < 4; ++i) {
                ull a = ap[i];
                fma2(acc[i][0], a, b0);
                fma2(acc[i][1], a, b1);
            }
        }
        __syncthreads();
    }

    float* Sb = g_attn + (size_t)b * N_ * N_;
#pragma unroll
    for (int i = 0; i < 4; ++i) {
        float2 a0 = up2(acc[i][0]);
        float2 a1 = up2(acc[i][1]);
        *(float4*)(Sb + (size_t)(n0 + ty * 4 + i) * N_ + m0 + tx * 4) =
            make_float4(a0.x, a0.y, a1.x, a1.y);
    }
}

// ---------------------------------------------------------------------------
// Kernel 3: row softmax over g_attn, in place. One block per (b, n) row.
// ---------------------------------------------------------------------------
__global__ __launch_bounds__(256) void k_softmax()
{
    float* p = g_attn + (size_t)blockIdx.x * N_;
    const int t = threadIdx.x;
    const int w = t >> 5, l = t & 31;
    __shared__ float red[8];

    float4 v = *(float4*)(p + t * 4);
    float m = fmaxf(fmaxf(v.x, v.y), fmaxf(v.z, v.w));
#pragma unroll
    for (int o = 16; o; o >>= 1) m = fmaxf(m, __shfl_xor_sync(0xffffffffu, m, o));
    if (l == 0) red[w] = m;
    __syncthreads();
    if (t == 0) {
        float mm = red[0];
#pragma unroll
        for (int i = 1; i < 8; ++i) mm = fmaxf(mm, red[i]);
        red[0] = mm;
    }
    __syncthreads();
    const float M = red[0];
    __syncthreads();

    v.x = __expf(v.x - M);
    v.y = __expf(v.y - M);
    v.z = __expf(v.z - M);
    v.w = __expf(v.w - M);
    float s = v.x + v.y + v.z + v.w;
#pragma unroll
    for (int o = 16; o; o >>= 1) s += __shfl_xor_sync(0xffffffffu, s, o);
    if (l == 0) red[w] = s;
    __syncthreads();
    if (t == 0) {
        float ss = red[0];
#pragma unroll
        for (int i = 1; i < 8; ++i) ss += red[i];
        red[0] = ss;
    }
    __syncthreads();
    const float inv = 1.0f / red[0];

    v.x *= inv; v.y *= inv; v.z *= inv; v.w *= inv;
    *(float4*)(p + t * 4) = v;
}

// ---------------------------------------------------------------------------
// Kernel 4: out[b,c,n] = gamma * sum_m attn[b,n,m] * vT[b,m,c] + x[b,c,n]
// Computed as O_T[c][n]: rows = c (from vT, contiguous dup load),
// cols = n (from attn, transposed load). Direct coalesced float4 epilogue.
// ---------------------------------------------------------------------------
__global__ __launch_bounds__(256) void k_out(
    const float* __restrict__ x, const float* __restrict__ gamma,
    float* __restrict__ out)
{
    __shared__ float sA[16][132];  // vT tile duplicated: [kk][2*cl]
    __shared__ float sB[16][68];   // attn tile transposed: [kk][nl]

    const int b  = blockIdx.z;
    const int c0 = blockIdx.y * 64;
    const int n0 = blockIdx.x * 64;

    const int t  = threadIdx.x;
    const int tx = t & 15, ty = t >> 4;

    // vT load mapping (contiguous in c)
    const int va_k = t >> 4;          // 0..15
    const int va_c = (t & 15) * 4;    // 0,4,..,60
    // attn load mapping (transposed)
    const int ab_n = t >> 2;          // 0..63
    const int ab_k = (t & 3) * 4;     // kk base

    const float* vb = g_v    + (size_t)b * N_ * C_ + c0;
    const float* Ab = g_attn + (size_t)b * N_ * N_;

    ull acc[4][2];
#pragma unroll
    for (int i = 0; i < 4; ++i) { acc[i][0] = 0ULL; acc[i][1] = 0ULL; }

    for (int k0 = 0; k0 < N_; k0 += 16) {
        float4 v4 = *(const float4*)(vb + (size_t)(k0 + va_k) * C_ + va_c);
        *(float4*)&sA[va_k][2 * va_c]     = make_float4(v4.x, v4.x, v4.y, v4.y);
        *(float4*)&sA[va_k][2 * va_c + 4] = make_float4(v4.z, v4.z, v4.w, v4.w);
        float4 a4 = *(const float4*)(Ab + (size_t)(n0 + ab_n) * N_ + k0 + ab_k);
        sB[ab_k + 0][ab_n] = a4.x;
        sB[ab_k + 1][ab_n] = a4.y;
        sB[ab_k + 2][ab_n] = a4.z;
        sB[ab_k + 3][ab_n] = a4.w;
        __syncthreads();
#pragma unroll
        for (int kk = 0; kk < 16; ++kk) {
            const ull* ap = (const ull*)&sA[kk][ty * 8];
            const ull* bp = (const ull*)&sB[kk][tx * 4];
            ull b0 = bp[0], b1 = bp[1];
#pragma unroll
            for (int i = 0; i < 4; ++i) {
                ull a = ap[i];
                fma2(acc[i][0], a, b0);
                fma2(acc[i][1], a, b1);
            }
        }
        __syncthreads();
    }

    const float gm = gamma[0];
#pragma unroll
    for (int i = 0; i < 4; ++i) {
        int c = c0 + ty * 4 + i;
        size_t off = ((size_t)b * C_ + c) * N_ + n0 + tx * 4;
        float4 xv = *(const float4*)(x + off);
        float2 a0 = up2(acc[i][0]);
        float2 a1 = up2(acc[i][1]);
        float4 o;
        o.x = fmaf(gm, a0.x, xv.x);
        o.y = fmaf(gm, a0.y, xv.y);
        o.z = fmaf(gm, a1.x, xv.z);
        o.w = fmaf(gm, a1.y, xv.w);
        *(float4*)(out + off) = o;
    }
}

// ---------------------------------------------------------------------------
extern "C" void kernel_launch(void* const* d_in, const int* in_sizes, int n_in,
                              void* d_out, int out_size)
{
    (void)in_sizes; (void)n_in; (void)out_size;
    const float* x     = (const float*)d_in[0];
    const float* Wq    = (const float*)d_in[1];
    const float* bq    = (const float*)d_in[2];
    const float* Wk    = (const float*)d_in[3];
    const float* bk    = (const float*)d_in[4];
    const float* Wv    = (const float*)d_in[5];
    const float* bv    = (const float*)d_in[6];
    const float* gamma = (const float*)d_in[7];
    float* out = (float*)d_out;

    k_proj<<<dim3(N_ / 64, 10, B_), 256>>>(x, Wq, bq, Wk, bk, Wv, bv);
    k_scores<<<dim3(N_ / 64, N_ / 64, B_), 256>>>();
    k_softmax<<<B_ * N_, 256>>>();
    k_out<<<dim3(N_ / 64, C_ / 64, B_), 256>>>(x, gamma, out);
}

// round 10
// speedup vs baseline: 1.0025x; 1.0007x over previous
#include <cuda_runtime.h>
#include <cuda_bf16.h>
#include <cstdint>

// Problem constants
#define B_  16
#define C_  512
#define N_  1024
#define D_  64

// Scratch (device globals per allocation rules): 4 + 4 + 32 + 64 = 104 MB
__device__ float g_q[(size_t)B_ * N_ * D_];              // [b][n][d]
__device__ float g_k[(size_t)B_ * N_ * D_];              // [b][n][d]
__device__ float g_v[(size_t)B_ * N_ * C_];              // vT: [b][m][c]
__device__ float g_attn[(size_t)B_ * N_ * N_];           // [b][n][m]

typedef unsigned long long ull;

__device__ __forceinline__ ull pk2(float lo, float hi) {
    ull r; asm("mov.b64 %0, {%1, %2};" : "=l"(r) : "f"(lo), "f"(hi)); return r;
}
__device__ __forceinline__ float2 up2(ull v) {
    float2 r; asm("mov.b64 {%0, %1}, %2;" : "=f"(r.x), "=f"(r.y) : "l"(v)); return r;
}
__device__ __forceinline__ void fma2(ull& d, ull a, ull b) {
    asm("fma.rn.f32x2 %0, %1, %2, %0;" : "+l"(d) : "l"(a), "l"(b));
}

// ---------------------------------------------------------------------------
// Kernel 1: fused QKV projection.  Y[oc, n] = sum_c W[oc,c] * x[b,c,n] + bias
// Tile: 64 oc x 64 n, block 256 threads, 4x4 micro-tile, k-chunks of 16.
// oc0 = 0   -> Wq -> g_q   [b][n][0..64)
// oc0 = 64  -> Wk -> g_k   [b][n][0..64)
// oc0 >=128 -> Wv -> g_v   [b][n][oc0-128 ..)
// ---------------------------------------------------------------------------
__global__ __launch_bounds__(256) void k_proj(
    const float* __restrict__ x,
    const float* __restrict__ Wq, const float* __restrict__ bq,
    const float* __restrict__ Wk, const float* __restrict__ bk,
    const float* __restrict__ Wv, const float* __restrict__ bv)
{
    __shared__ float sA[16][132];  // W tile, value-duplicated: [kk][2*ocl {lo,hi}]
    __shared__ float sB[16][68];   // x tile: [kk][nl]
    __shared__ float sO[64][65];   // output restage [nl][ocl]

    const int b   = blockIdx.z;
    const int oc0 = blockIdx.y * 64;
    const int n0  = blockIdx.x * 64;

    const float* Wsrc; const float* bias; float* dst; int dstride;
    if (oc0 == 0)       { Wsrc = Wq; bias = bq; dst = g_q + (size_t)b * N_ * D_; dstride = D_; }
    else if (oc0 == 64) { Wsrc = Wk; bias = bk; dst = g_k + (size_t)b * N_ * D_; dstride = D_; }
    else                { Wsrc = Wv + (size_t)(oc0 - 128) * C_; bias = bv + (oc0 - 128);
                          dst = g_v + (size_t)b * N_ * C_ + (oc0 - 128); dstride = C_; }

    const int t  = threadIdx.x;
    const int tx = t & 15, ty = t >> 4;

    // load mappings
    const int la_r = t >> 2;          // 0..63  W row within tile
    const int la_c = (t & 3) * 4;     // kk base
    const int lb_k = t >> 4;          // 0..15
    const int lb_n = (t & 15) * 4;    // 0,4,..,60

    const float* xb = x + (size_t)b * C_ * N_ + n0;

    ull acc[4][2];
#pragma unroll
    for (int i = 0; i < 4; ++i) { acc[i][0] = 0ULL; acc[i][1] = 0ULL; }

    for (int k0 = 0; k0 < C_; k0 += 16) {
        float4 w4 = *(const float4*)(Wsrc + (size_t)la_r * C_ + k0 + la_c);
        *(ull*)&sA[la_c + 0][2 * la_r] = pk2(w4.x, w4.x);
        *(ull*)&sA[la_c + 1][2 * la_r] = pk2(w4.y, w4.y);
        *(ull*)&sA[la_c + 2][2 * la_r] = pk2(w4.z, w4.z);
        *(ull*)&sA[la_c + 3][2 * la_r] = pk2(w4.w, w4.w);
        float4 x4 = *(const float4*)(xb + (size_t)(k0 + lb_k) * N_ + lb_n);
        *(float4*)&sB[lb_k][lb_n] = x4;
        __syncthreads();
#pragma unroll
        for (int kk = 0; kk < 16; ++kk) {
            const ull* ap = (const ull*)&sA[kk][ty * 8];
            const ull* bp = (const ull*)&sB[kk][tx * 4];
            ull b0 = bp[0], b1 = bp[1];
#pragma unroll
            for (int i = 0; i < 4; ++i) {
                ull a = ap[i];
                fma2(acc[i][0], a, b0);
                fma2(acc[i][1], a, b1);
            }
        }
        __syncthreads();
    }

    // bias + restage to smem for coalesced transposed write
    float4 bi4 = *(const float4*)(bias + ty * 4);
    float bia[4] = {bi4.x, bi4.y, bi4.z, bi4.w};
#pragma unroll
    for (int i = 0; i < 4; ++i) {
        float2 a0 = up2(acc[i][0]);
        float2 a1 = up2(acc[i][1]);
        sO[tx * 4 + 0][ty * 4 + i] = a0.x + bia[i];
        sO[tx * 4 + 1][ty * 4 + i] = a0.y + bia[i];
        sO[tx * 4 + 2][ty * 4 + i] = a1.x + bia[i];
        sO[tx * 4 + 3][ty * 4 + i] = a1.y + bia[i];
    }
    __syncthreads();
#pragma unroll
    for (int s = 0; s < 16; ++s) {
        int idx = s * 256 + t;
        int nl  = idx >> 6;
        int ocl = idx & 63;
        dst[(size_t)(n0 + nl) * dstride + ocl] = sO[nl][ocl];
    }
}

// ---------------------------------------------------------------------------
// Kernel 2: scores S[b,n,m] = sum_d q[b,n,d] * k[b,m,d]   (NT GEMM, K=64)
// ---------------------------------------------------------------------------
__global__ __launch_bounds__(256) void k_scores()
{
    __shared__ float sA[16][132];  // q tile duplicated: [kk][2*nl]
    __shared__ float sB[16][68];   // k tile transposed: [kk][ml]

    const int b  = blockIdx.z;
    const int n0 = blockIdx.y * 64;
    const int m0 = blockIdx.x * 64;

    const int t  = threadIdx.x;
    const int tx = t & 15, ty = t >> 4;
    const int lr = t >> 2;          // 0..63 row within tile
    const int lc = (t & 3) * 4;     // kk base

    const float* qb = g_q + (size_t)b * N_ * D_;
    const float* kb = g_k + (size_t)b * N_ * D_;

    ull acc[4][2];
#pragma unroll
    for (int i = 0; i < 4; ++i) { acc[i][0] = 0ULL; acc[i][1] = 0ULL; }

    for (int k0 = 0; k0 < D_; k0 += 16) {
        float4 q4 = *(const float4*)(qb + (size_t)(n0 + lr) * D_ + k0 + lc);
        *(ull*)&sA[lc + 0][2 * lr] = pk2(q4.x, q4.x);
        *(ull*)&sA[lc + 1][2 * lr] = pk2(q4.y, q4.y);
        *(ull*)&sA[lc + 2][2 * lr] = pk2(q4.z, q4.z);
        *(ull*)&sA[lc + 3][2 * lr] = pk2(q4.w, q4.w);
        float4 k4 = *(const float4*)(kb + (size_t)(m0 + lr) * D_ + k0 + lc);
        sB[lc + 0][lr] = k4.x;
        sB[lc + 1][lr] = k4.y;
        sB[lc + 2][lr] = k4.z;
        sB[lc + 3][lr] = k4.w;
        __syncthreads();
#pragma unroll
        for (int kk = 0; kk < 16; ++kk) {
            const ull* ap = (const ull*)&sA[kk][ty * 8];
            const ull* bp = (const ull*)&sB[kk][tx * 4];
            ull b0 = bp[0], b1 = bp[1];
#pragma unroll
            for (int i = 0; i < 4; ++i) {
                ull a = ap[i];
                fma2(acc[i][0], a, b0);
                fma2(acc[i][1], a, b1);
            }
        }
        __syncthreads();
    }

    float* Sb = g_attn + (size_t)b * N_ * N_;
#pragma unroll
    for (int i = 0; i < 4; ++i) {
        float2 a0 = up2(acc[i][0]);
        float2 a1 = up2(acc[i][1]);
        *(float4*)(Sb + (size_t)(n0 + ty * 4 + i) * N_ + m0 + tx * 4) =
            make_float4(a0.x, a0.y, a1.x, a1.y);
    }
}

// ---------------------------------------------------------------------------
// Kernel 3: row softmax over g_attn, in place. One block per (b, n) row.
// ---------------------------------------------------------------------------
__global__ __launch_bounds__(256) void k_softmax()
{
    float* p = g_attn + (size_t)blockIdx.x * N_;
    const int t = threadIdx.x;
    const int w = t >> 5, l = t & 31;
    __shared__ float red[8];

    float4 v = *(float4*)(p + t * 4);
    float m = fmaxf(fmaxf(v.x, v.y), fmaxf(v.z, v.w));
#pragma unroll
    for (int o = 16; o; o >>= 1) m = fmaxf(m, __shfl_xor_sync(0xffffffffu, m, o));
    if (l == 0) red[w] = m;
    __syncthreads();
    if (t == 0) {
        float mm = red[0];
#pragma unroll
        for (int i = 1; i < 8; ++i) mm = fmaxf(mm, red[i]);
        red[0] = mm;
    }
    __syncthreads();
    const float M = red[0];
    __syncthreads();

    v.x = __expf(v.x - M);
    v.y = __expf(v.y - M);
    v.z = __expf(v.z - M);
    v.w = __expf(v.w - M);
    float s = v.x + v.y + v.z + v.w;
#pragma unroll
    for (int o = 16; o; o >>= 1) s += __shfl_xor_sync(0xffffffffu, s, o);
    if (l == 0) red[w] = s;
    __syncthreads();
    if (t == 0) {
        float ss = red[0];
#pragma unroll
        for (int i = 1; i < 8; ++i) ss += red[i];
        red[0] = ss;
    }
    __syncthreads();
    const float inv = 1.0f / red[0];

    v.x *= inv; v.y *= inv; v.z *= inv; v.w *= inv;
    *(float4*)(p + t * 4) = v;
}

// ---------------------------------------------------------------------------
// Kernel 4: out[b,c,n] = gamma * sum_m attn[b,n,m] * vT[b,m,c] + x[b,c,n]
// Computed as O_T[c][n]: rows = c (from vT, contiguous dup load),
// cols = n (from attn, transposed load). Direct coalesced float4 epilogue.
// ---------------------------------------------------------------------------
__global__ __launch_bounds__(256) void k_out(
    const float* __restrict__ x, const float* __restrict__ gamma,
    float* __restrict__ out)
{
    __shared__ float sA[16][132];  // vT tile duplicated: [kk][2*cl]
    __shared__ float sB[16][68];   // attn tile transposed: [kk][nl]

    const int b  = blockIdx.z;
    const int c0 = blockIdx.y * 64;
    const int n0 = blockIdx.x * 64;

    const int t  = threadIdx.x;
    const int tx = t & 15, ty = t >> 4;

    // vT load mapping (contiguous in c)
    const int va_k = t >> 4;          // 0..15
    const int va_c = (t & 15) * 4;    // 0,4,..,60
    // attn load mapping (transposed)
    const int ab_n = t >> 2;          // 0..63
    const int ab_k = (t & 3) * 4;     // kk base

    const float* vb = g_v    + (size_t)b * N_ * C_ + c0;
    const float* Ab = g_attn + (size_t)b * N_ * N_;

    ull acc[4][2];
#pragma unroll
    for (int i = 0; i < 4; ++i) { acc[i][0] = 0ULL; acc[i][1] = 0ULL; }

    for (int k0 = 0; k0 < N_; k0 += 16) {
        float4 v4 = *(const float4*)(vb + (size_t)(k0 + va_k) * C_ + va_c);
        *(float4*)&sA[va_k][2 * va_c]     = make_float4(v4.x, v4.x, v4.y, v4.y);
        *(float4*)&sA[va_k][2 * va_c + 4] = make_float4(v4.z, v4.z, v4.w, v4.w);
        float4 a4 = *(const float4*)(Ab + (size_t)(n0 + ab_n) * N_ + k0 + ab_k);
        sB[ab_k + 0][ab_n] = a4.x;
        sB[ab_k + 1][ab_n] = a4.y;
        sB[ab_k + 2][ab_n] = a4.z;
        sB[ab_k + 3][ab_n] = a4.w;
        __syncthreads();
#pragma unroll
        for (int kk = 0; kk < 16; ++kk) {
            const ull* ap = (const ull*)&sA[kk][ty * 8];
            const ull* bp = (const ull*)&sB[kk][tx * 4];
            ull b0 = bp[0], b1 = bp[1];
#pragma unroll
            for (int i = 0; i < 4; ++i) {
                ull a = ap[i];
                fma2(acc[i][0], a, b0);
                fma2(acc[i][1], a, b1);
            }
        }
        __syncthreads();
    }

    const float gm = gamma[0];
#pragma unroll
    for (int i = 0; i < 4; ++i) {
        int c = c0 + ty * 4 + i;
        size_t off = ((size_t)b * C_ + c) * N_ + n0 + tx * 4;
        float4 xv = *(const float4*)(x + off);
        float2 a0 = up2(acc[i][0]);
        float2 a1 = up2(acc[i][1]);
        float4 o;
        o.x = fmaf(gm, a0.x, xv.x);
        o.y = fmaf(gm, a0.y, xv.y);
        o.z = fmaf(gm, a1.x, xv.z);
        o.w = fmaf(gm, a1.y, xv.w);
        *(float4*)(out + off) = o;
    }
}

// ---------------------------------------------------------------------------
extern "C" void kernel_launch(void* const* d_in, const int* in_sizes, int n_in,
                              void* d_out, int out_size)
{
    (void)in_sizes; (void)n_in; (void)out_size;
    const float* x     = (const float*)d_in[0];
    const float* Wq    = (const float*)d_in[1];
    const float* bq    = (const float*)d_in[2];
    const float* Wk    = (const float*)d_in[3];
    const float* bk    = (const float*)d_in[4];
    const float* Wv    = (const float*)d_in[5];
    const float* bv    = (const float*)d_in[6];
    const float* gamma = (const float*)d_in[7];
    float* out = (float*)d_out;

    k_proj<<<dim3(N_ / 64, 10, B_), 256>>>(x, Wq, bq, Wk, bk, Wv, bv);
    k_scores<<<dim3(N_ / 64, N_ / 64, B_), 256>>>();
    k_softmax<<<B_ * N_, 256>>>();
    k_out<<<dim3(N_ / 64, C_ / 64, B_), 256>>>(x, gamma, out);
}